// round 10
// baseline (speedup 1.0000x reference)
#include <cuda_runtime.h>
#include <cuda_bf16.h>
#include <cstdint>

// AGNNConv:
//   Xp = X @ W;  attn[e] = dot(Xp[row[e]], Xp[col[e]]) * w
//   out[i] = sum_{e: row[e]==i} attn[e] * Xp[col[e]]
// Inputs: X [N*64 f32], W [64*64 f32], attention_w [1 f32],
//         row [E i32 sorted], col [E i32].  Output: out [N*64 f32]

#define D 64
#define MAX_NODES 50000
#define EPG 16              // edges per 8-lane group
#define EPW (4 * EPG)       // 64 edges per warp
#define RPB 128             // rows per block (gemm)
#define XS_STRIDE 68
#define BPK 34

__device__ float4 g_Xp4[MAX_NODES * (D / 4)];

// ---------------------------------------------------------------------------
// bf16 split helpers
// ---------------------------------------------------------------------------
__device__ __forceinline__ uint32_t pack_bf16(float x, float y) {
    __nv_bfloat162 p = __floats2bfloat162_rn(x, y);
    return *reinterpret_cast<uint32_t*>(&p);
}
__device__ __forceinline__ void split_bf16(float x, float& h, float& l) {
    __nv_bfloat16 bh = __float2bfloat16_rn(x);
    h = __bfloat162float(bh);
    l = x - h;
}
__device__ __forceinline__ void mma16816(float* d, const uint32_t* a,
                                         uint32_t b0, uint32_t b1) {
    asm volatile(
        "mma.sync.aligned.m16n8k16.row.col.f32.bf16.bf16.f32 "
        "{%0,%1,%2,%3}, {%4,%5,%6,%7}, {%8,%9}, {%0,%1,%2,%3};"
        : "+f"(d[0]), "+f"(d[1]), "+f"(d[2]), "+f"(d[3])
        : "r"(a[0]), "r"(a[1]), "r"(a[2]), "r"(a[3]), "r"(b0), "r"(b1));
}

// ---------------------------------------------------------------------------
// Kernel 1: Xp = X @ W + zero out, tensor cores (bf16 3-term split).
// Validated R9 version, unchanged.
// ---------------------------------------------------------------------------
__global__ void __launch_bounds__(256)
gemm_zero_kernel(const float4* __restrict__ X4, const float* __restrict__ W,
                 float2* __restrict__ out2, int n_nodes)
{
    __shared__ float    Xs[RPB * XS_STRIDE];
    __shared__ uint32_t Bh[D * BPK];
    __shared__ uint32_t Bl[D * BPK];

    int t  = threadIdx.x;
    int r0 = blockIdx.x * RPB;

    #pragma unroll
    for (int i = 0; i < 8; ++i) {
        int idx = t + 256 * i;
        int k2 = idx >> 6;
        int n  = idx & 63;
        float w0 = W[(2 * k2) * D + n];
        float w1 = W[(2 * k2 + 1) * D + n];
        float h0, l0, h1, l1;
        split_bf16(w0, h0, l0);
        split_bf16(w1, h1, l1);
        Bh[n * BPK + k2] = pack_bf16(h0, h1);
        Bl[n * BPK + k2] = pack_bf16(l0, l1);
    }

    #pragma unroll
    for (int i = 0; i < 8; ++i) {
        int idx4 = t + 256 * i;
        int r  = idx4 >> 4;
        int k4 = idx4 & 15;
        float4 v = (r0 + r < n_nodes) ? X4[(r0 + r) * 16 + k4]
                                      : make_float4(0.f, 0.f, 0.f, 0.f);
        *reinterpret_cast<float4*>(&Xs[r * XS_STRIDE + k4 * 4]) = v;
    }
    __syncthreads();

    int warp = t >> 5;
    int lane = t & 31;
    int g  = lane >> 2;
    int tq = lane & 3;
    int wbase = warp * 16;

    float acc[8][4];
    #pragma unroll
    for (int j = 0; j < 8; ++j)
        #pragma unroll
        for (int k = 0; k < 4; ++k) acc[j][k] = 0.f;

    const float* row0 = &Xs[(wbase + g) * XS_STRIDE];
    const float* row1 = &Xs[(wbase + g + 8) * XS_STRIDE];

    #pragma unroll
    for (int s = 0; s < 4; ++s) {
        float2 v00 = *reinterpret_cast<const float2*>(&row0[16 * s + 2 * tq]);
        float2 v10 = *reinterpret_cast<const float2*>(&row1[16 * s + 2 * tq]);
        float2 v01 = *reinterpret_cast<const float2*>(&row0[16 * s + 2 * tq + 8]);
        float2 v11 = *reinterpret_cast<const float2*>(&row1[16 * s + 2 * tq + 8]);

        float h, l, h2, l2;
        uint32_t Ah[4], Al[4];
        split_bf16(v00.x, h, l); split_bf16(v00.y, h2, l2);
        Ah[0] = pack_bf16(h, h2);  Al[0] = pack_bf16(l, l2);
        split_bf16(v10.x, h, l); split_bf16(v10.y, h2, l2);
        Ah[1] = pack_bf16(h, h2);  Al[1] = pack_bf16(l, l2);
        split_bf16(v01.x, h, l); split_bf16(v01.y, h2, l2);
        Ah[2] = pack_bf16(h, h2);  Al[2] = pack_bf16(l, l2);
        split_bf16(v11.x, h, l); split_bf16(v11.y, h2, l2);
        Ah[3] = pack_bf16(h, h2);  Al[3] = pack_bf16(l, l2);

        #pragma unroll
        for (int j = 0; j < 8; ++j) {
            int nrow = (8 * j + g) * BPK + 8 * s + tq;
            uint32_t b0h = Bh[nrow];
            uint32_t b1h = Bh[nrow + 4];
            uint32_t b0l = Bl[nrow];
            uint32_t b1l = Bl[nrow + 4];
            mma16816(acc[j], Ah, b0h, b1h);
            mma16816(acc[j], Ah, b0l, b1l);
            mma16816(acc[j], Al, b0h, b1h);
        }
    }

    float2* Xp2 = reinterpret_cast<float2*>(g_Xp4);
    float2 z2 = make_float2(0.f, 0.f);
    int ra = r0 + wbase + g;
    int rb = ra + 8;
    #pragma unroll
    for (int j = 0; j < 8; ++j) {
        int cpair = (8 * j + 2 * tq) >> 1;
        if (ra < n_nodes) {
            Xp2[ra * 32 + cpair]  = make_float2(acc[j][0], acc[j][1]);
            out2[ra * 32 + cpair] = z2;
        }
        if (rb < n_nodes) {
            Xp2[rb * 32 + cpair]  = make_float2(acc[j][2], acc[j][3]);
            out2[rb * 32 + cpair] = z2;
        }
    }
}

// ---------------------------------------------------------------------------
// Kernel 2a (FAST, requires n_edges % EPW == 0): R4 skeleton + int4 index
// loads (2 LDG per 4 edges instead of 8 scalar LDG) + w-multiply hoisted to
// the flush. Warp = 4 groups of 8 lanes; lane q owns quads q, q+8.
// ---------------------------------------------------------------------------
#define EDGE_STEP(RR, CC)                                                     \
    {                                                                         \
        int r_ = (RR); int c_ = (CC);                                         \
        if (r_ != cur_r) {                                                    \
            atomicAdd(&out4[cur_r * 16 + q],                                  \
                      make_float4(acc0.x * w, acc0.y * w, acc0.z * w, acc0.w * w)); \
            atomicAdd(&out4[cur_r * 16 + 8 + q],                              \
                      make_float4(acc1.x * w, acc1.y * w, acc1.z * w, acc1.w * w)); \
            acc0 = make_float4(0.f, 0.f, 0.f, 0.f);                           \
            acc1 = make_float4(0.f, 0.f, 0.f, 0.f);                           \
            cur_r = r_;                                                       \
            xr0 = g_Xp4[r_ * 16 + q];                                         \
            xr1 = g_Xp4[r_ * 16 + 8 + q];                                     \
        }                                                                     \
        float4 xc0 = g_Xp4[c_ * 16 + q];                                      \
        float4 xc1 = g_Xp4[c_ * 16 + 8 + q];                                  \
        float p = xc0.x * xr0.x + xc0.y * xr0.y + xc0.z * xr0.z + xc0.w * xr0.w \
                + xc1.x * xr1.x + xc1.y * xr1.y + xc1.z * xr1.z + xc1.w * xr1.w; \
        p += __shfl_xor_sync(0xFFFFFFFFu, p, 4);                              \
        p += __shfl_xor_sync(0xFFFFFFFFu, p, 2);                              \
        p += __shfl_xor_sync(0xFFFFFFFFu, p, 1);                              \
        acc0.x = fmaf(p, xc0.x, acc0.x);                                      \
        acc0.y = fmaf(p, xc0.y, acc0.y);                                      \
        acc0.z = fmaf(p, xc0.z, acc0.z);                                      \
        acc0.w = fmaf(p, xc0.w, acc0.w);                                      \
        acc1.x = fmaf(p, xc1.x, acc1.x);                                      \
        acc1.y = fmaf(p, xc1.y, acc1.y);                                      \
        acc1.z = fmaf(p, xc1.z, acc1.z);                                      \
        acc1.w = fmaf(p, xc1.w, acc1.w);                                      \
    }

__global__ void __launch_bounds__(256)
edge_kernel_fast(const int* __restrict__ row, const int* __restrict__ col,
                 const float* __restrict__ attn_w, float4* __restrict__ out4,
                 int n_edges)
{
    int warp_id = (blockIdx.x * blockDim.x + threadIdx.x) >> 5;
    int lane    = threadIdx.x & 31;
    int q       = lane & 7;

    int e0 = warp_id * EPW + (lane >> 3) * EPG;
    if (e0 >= n_edges) return;

    const int4* row4 = reinterpret_cast<const int4*>(row + e0);
    const int4* col4 = reinterpret_cast<const int4*>(col + e0);
    const float w = __ldg(attn_w);

    int4 rv = row4[0];
    int4 cv = col4[0];

    int cur_r = rv.x;
    float4 xr0 = g_Xp4[cur_r * 16 + q];
    float4 xr1 = g_Xp4[cur_r * 16 + 8 + q];
    float4 acc0 = make_float4(0.f, 0.f, 0.f, 0.f);
    float4 acc1 = make_float4(0.f, 0.f, 0.f, 0.f);

    #pragma unroll
    for (int j = 0; j < EPG / 4; ++j) {
        EDGE_STEP(rv.x, cv.x)
        EDGE_STEP(rv.y, cv.y)
        EDGE_STEP(rv.z, cv.z)
        EDGE_STEP(rv.w, cv.w)
        if (j + 1 < EPG / 4) {
            rv = row4[j + 1];
            cv = col4[j + 1];
        }
    }

    atomicAdd(&out4[cur_r * 16 + q],
              make_float4(acc0.x * w, acc0.y * w, acc0.z * w, acc0.w * w));
    atomicAdd(&out4[cur_r * 16 + 8 + q],
              make_float4(acc1.x * w, acc1.y * w, acc1.z * w, acc1.w * w));
}

// ---------------------------------------------------------------------------
// Kernel 2b (generic fallback, any n_edges): exact R4/R8 kernel.
// ---------------------------------------------------------------------------
__global__ void __launch_bounds__(256)
edge_kernel(const int* __restrict__ row, const int* __restrict__ col,
            const float* __restrict__ attn_w, float4* __restrict__ out4,
            int n_edges)
{
    int warp_id = (blockIdx.x * blockDim.x + threadIdx.x) >> 5;
    int lane    = threadIdx.x & 31;
    int g       = lane >> 3;
    int q       = lane & 7;

    int wbase = warp_id * EPW;
    if (wbase >= n_edges) return;

    int e0 = wbase + g * EPG;
    bool any = e0 < n_edges;
    int e_end = any ? min(e0 + EPG, n_edges) : e0;

    const float w = __ldg(attn_w);

    int cur_r = any ? row[e0] : 0;
    float4 xr0 = g_Xp4[cur_r * 16 + q];
    float4 xr1 = g_Xp4[cur_r * 16 + 8 + q];
    float4 acc0 = make_float4(0.f, 0.f, 0.f, 0.f);
    float4 acc1 = make_float4(0.f, 0.f, 0.f, 0.f);

    #pragma unroll 4
    for (int i = 0; i < EPG; ++i) {
        int e = e0 + i;
        bool valid = any && (e < e_end);
        int ec = valid ? e : (any ? e0 : 0);

        int r = row[ec];
        int c = col[ec];

        if (valid && r != cur_r) {
            atomicAdd(&out4[cur_r * 16 + q],     acc0);
            atomicAdd(&out4[cur_r * 16 + 8 + q], acc1);
            acc0 = make_float4(0.f, 0.f, 0.f, 0.f);
            acc1 = make_float4(0.f, 0.f, 0.f, 0.f);
            cur_r = r;
            xr0 = g_Xp4[r * 16 + q];
            xr1 = g_Xp4[r * 16 + 8 + q];
        }

        float4 xc0 = g_Xp4[c * 16 + q];
        float4 xc1 = g_Xp4[c * 16 + 8 + q];

        float p = xc0.x * xr0.x + xc0.y * xr0.y + xc0.z * xr0.z + xc0.w * xr0.w
                + xc1.x * xr1.x + xc1.y * xr1.y + xc1.z * xr1.z + xc1.w * xr1.w;

        p += __shfl_xor_sync(0xFFFFFFFFu, p, 4);
        p += __shfl_xor_sync(0xFFFFFFFFu, p, 2);
        p += __shfl_xor_sync(0xFFFFFFFFu, p, 1);

        if (valid) {
            float a = p * w;
            acc0.x = fmaf(a, xc0.x, acc0.x);
            acc0.y = fmaf(a, xc0.y, acc0.y);
            acc0.z = fmaf(a, xc0.z, acc0.z);
            acc0.w = fmaf(a, xc0.w, acc0.w);
            acc1.x = fmaf(a, xc1.x, acc1.x);
            acc1.y = fmaf(a, xc1.y, acc1.y);
            acc1.z = fmaf(a, xc1.z, acc1.z);
            acc1.w = fmaf(a, xc1.w, acc1.w);
        }
    }

    if (any) {
        atomicAdd(&out4[cur_r * 16 + q],     acc0);
        atomicAdd(&out4[cur_r * 16 + 8 + q], acc1);
    }
}

// ---------------------------------------------------------------------------
extern "C" void kernel_launch(void* const* d_in, const int* in_sizes, int n_in,
                              void* d_out, int out_size)
{
    const float4* X4 = (const float4*)d_in[0];
    const float*  W  = (const float*)d_in[1];
    const float*  aw = (const float*)d_in[2];
    const int*   row = (const int*)d_in[3];
    const int*   col = (const int*)d_in[4];

    int n_nodes = in_sizes[0] / D;
    int n_edges = in_sizes[3];

    gemm_zero_kernel<<<(n_nodes + RPB - 1) / RPB, 256>>>(
        X4, W, (float2*)d_out, n_nodes);

    int n_warps  = (n_edges + EPW - 1) / EPW;
    int n_blocks = (n_warps + 7) / 8;
    if (n_edges % EPW == 0) {
        edge_kernel_fast<<<n_blocks, 256>>>(row, col, aw, (float4*)d_out, n_edges);
    } else {
        edge_kernel<<<n_blocks, 256>>>(row, col, aw, (float4*)d_out, n_edges);
    }
}

// round 11
// speedup vs baseline: 1.0125x; 1.0125x over previous
#include <cuda_runtime.h>
#include <cuda_bf16.h>
#include <cstdint>

// AGNNConv:
//   Xp = X @ W;  attn[e] = dot(Xp[row[e]], Xp[col[e]]) * w
//   out[i] = sum_{e: row[e]==i} attn[e] * Xp[col[e]]
// Inputs: X [N*64 f32], W [64*64 f32], attention_w [1 f32],
//         row [E i32 sorted], col [E i32].  Output: out [N*64 f32]

#define D 64
#define MAX_NODES 50000
#define EPG 16              // edges per 8-lane group
#define EPW (4 * EPG)       // 64 edges per warp
#define RPB 128             // rows per block (gemm)
#define XS_STRIDE 68
#define BPK 34

__device__ float4 g_Xp4[MAX_NODES * (D / 4)];

// ---------------------------------------------------------------------------
// bf16 split helpers
// ---------------------------------------------------------------------------
__device__ __forceinline__ uint32_t pack_bf16(float x, float y) {
    __nv_bfloat162 p = __floats2bfloat162_rn(x, y);
    return *reinterpret_cast<uint32_t*>(&p);
}
__device__ __forceinline__ void split_bf16(float x, float& h, float& l) {
    __nv_bfloat16 bh = __float2bfloat16_rn(x);
    h = __bfloat162float(bh);
    l = x - h;
}
__device__ __forceinline__ void mma16816(float* d, const uint32_t* a,
                                         uint32_t b0, uint32_t b1) {
    asm volatile(
        "mma.sync.aligned.m16n8k16.row.col.f32.bf16.bf16.f32 "
        "{%0,%1,%2,%3}, {%4,%5,%6,%7}, {%8,%9}, {%0,%1,%2,%3};"
        : "+f"(d[0]), "+f"(d[1]), "+f"(d[2]), "+f"(d[3])
        : "r"(a[0]), "r"(a[1]), "r"(a[2]), "r"(a[3]), "r"(b0), "r"(b1));
}

// ---------------------------------------------------------------------------
// Kernel 1: Xp = X @ W + zero out, tensor cores (bf16 3-term split).
// Validated R9 version, unchanged.
// ---------------------------------------------------------------------------
__global__ void __launch_bounds__(256)
gemm_zero_kernel(const float4* __restrict__ X4, const float* __restrict__ W,
                 float2* __restrict__ out2, int n_nodes)
{
    __shared__ float    Xs[RPB * XS_STRIDE];
    __shared__ uint32_t Bh[D * BPK];
    __shared__ uint32_t Bl[D * BPK];

    int t  = threadIdx.x;
    int r0 = blockIdx.x * RPB;

    #pragma unroll
    for (int i = 0; i < 8; ++i) {
        int idx = t + 256 * i;
        int k2 = idx >> 6;
        int n  = idx & 63;
        float w0 = W[(2 * k2) * D + n];
        float w1 = W[(2 * k2 + 1) * D + n];
        float h0, l0, h1, l1;
        split_bf16(w0, h0, l0);
        split_bf16(w1, h1, l1);
        Bh[n * BPK + k2] = pack_bf16(h0, h1);
        Bl[n * BPK + k2] = pack_bf16(l0, l1);
    }

    #pragma unroll
    for (int i = 0; i < 8; ++i) {
        int idx4 = t + 256 * i;
        int r  = idx4 >> 4;
        int k4 = idx4 & 15;
        float4 v = (r0 + r < n_nodes) ? X4[(r0 + r) * 16 + k4]
                                      : make_float4(0.f, 0.f, 0.f, 0.f);
        *reinterpret_cast<float4*>(&Xs[r * XS_STRIDE + k4 * 4]) = v;
    }
    __syncthreads();

    int warp = t >> 5;
    int lane = t & 31;
    int g  = lane >> 2;
    int tq = lane & 3;
    int wbase = warp * 16;

    float acc[8][4];
    #pragma unroll
    for (int j = 0; j < 8; ++j)
        #pragma unroll
        for (int k = 0; k < 4; ++k) acc[j][k] = 0.f;

    const float* row0 = &Xs[(wbase + g) * XS_STRIDE];
    const float* row1 = &Xs[(wbase + g + 8) * XS_STRIDE];

    #pragma unroll
    for (int s = 0; s < 4; ++s) {
        float2 v00 = *reinterpret_cast<const float2*>(&row0[16 * s + 2 * tq]);
        float2 v10 = *reinterpret_cast<const float2*>(&row1[16 * s + 2 * tq]);
        float2 v01 = *reinterpret_cast<const float2*>(&row0[16 * s + 2 * tq + 8]);
        float2 v11 = *reinterpret_cast<const float2*>(&row1[16 * s + 2 * tq + 8]);

        float h, l, h2, l2;
        uint32_t Ah[4], Al[4];
        split_bf16(v00.x, h, l); split_bf16(v00.y, h2, l2);
        Ah[0] = pack_bf16(h, h2);  Al[0] = pack_bf16(l, l2);
        split_bf16(v10.x, h, l); split_bf16(v10.y, h2, l2);
        Ah[1] = pack_bf16(h, h2);  Al[1] = pack_bf16(l, l2);
        split_bf16(v01.x, h, l); split_bf16(v01.y, h2, l2);
        Ah[2] = pack_bf16(h, h2);  Al[2] = pack_bf16(l, l2);
        split_bf16(v11.x, h, l); split_bf16(v11.y, h2, l2);
        Ah[3] = pack_bf16(h, h2);  Al[3] = pack_bf16(l, l2);

        #pragma unroll
        for (int j = 0; j < 8; ++j) {
            int nrow = (8 * j + g) * BPK + 8 * s + tq;
            uint32_t b0h = Bh[nrow];
            uint32_t b1h = Bh[nrow + 4];
            uint32_t b0l = Bl[nrow];
            uint32_t b1l = Bl[nrow + 4];
            mma16816(acc[j], Ah, b0h, b1h);
            mma16816(acc[j], Ah, b0l, b1l);
            mma16816(acc[j], Al, b0h, b1h);
        }
    }

    float2* Xp2 = reinterpret_cast<float2*>(g_Xp4);
    float2 z2 = make_float2(0.f, 0.f);
    int ra = r0 + wbase + g;
    int rb = ra + 8;
    #pragma unroll
    for (int j = 0; j < 8; ++j) {
        int cpair = (8 * j + 2 * tq) >> 1;
        if (ra < n_nodes) {
            Xp2[ra * 32 + cpair]  = make_float2(acc[j][0], acc[j][1]);
            out2[ra * 32 + cpair] = z2;
        }
        if (rb < n_nodes) {
            Xp2[rb * 32 + cpair]  = make_float2(acc[j][2], acc[j][3]);
            out2[rb * 32 + cpair] = z2;
        }
    }
}

// ---------------------------------------------------------------------------
// Kernel 2: edge SDDMM + register SpMM scatter — R4/R8 structure, with all
// g_Xp4 reads routed through __ldg (read-only / non-coherent path). g_Xp4 is
// never written here, and __ldg tells ptxas these loads cannot alias the
// atomicAdd stores to out4 — so it can hoist the next edge's loads above the
// flush branch and pipeline the L2 latency itself (register-neutral).
// ---------------------------------------------------------------------------
__global__ void __launch_bounds__(256)
edge_kernel(const int* __restrict__ row, const int* __restrict__ col,
            const float* __restrict__ attn_w, float4* __restrict__ out4,
            int n_edges)
{
    int warp_id = (blockIdx.x * blockDim.x + threadIdx.x) >> 5;
    int lane    = threadIdx.x & 31;
    int g       = lane >> 3;
    int q       = lane & 7;

    int wbase = warp_id * EPW;
    if (wbase >= n_edges) return;

    int e0 = wbase + g * EPG;
    bool any = e0 < n_edges;
    int e_end = any ? min(e0 + EPG, n_edges) : e0;

    const float w = __ldg(attn_w);

    int cur_r = any ? __ldg(&row[e0]) : 0;
    float4 xr0 = __ldg(&g_Xp4[cur_r * 16 + q]);
    float4 xr1 = __ldg(&g_Xp4[cur_r * 16 + 8 + q]);
    float4 acc0 = make_float4(0.f, 0.f, 0.f, 0.f);
    float4 acc1 = make_float4(0.f, 0.f, 0.f, 0.f);

    #pragma unroll 4
    for (int i = 0; i < EPG; ++i) {
        int e = e0 + i;
        bool valid = any && (e < e_end);
        int ec = valid ? e : (any ? e0 : 0);

        int r = __ldg(&row[ec]);
        int c = __ldg(&col[ec]);

        if (valid && r != cur_r) {
            atomicAdd(&out4[cur_r * 16 + q],     acc0);
            atomicAdd(&out4[cur_r * 16 + 8 + q], acc1);
            acc0 = make_float4(0.f, 0.f, 0.f, 0.f);
            acc1 = make_float4(0.f, 0.f, 0.f, 0.f);
            cur_r = r;
            xr0 = __ldg(&g_Xp4[r * 16 + q]);
            xr1 = __ldg(&g_Xp4[r * 16 + 8 + q]);
        }

        float4 xc0 = __ldg(&g_Xp4[c * 16 + q]);
        float4 xc1 = __ldg(&g_Xp4[c * 16 + 8 + q]);

        float p = xc0.x * xr0.x + xc0.y * xr0.y + xc0.z * xr0.z + xc0.w * xr0.w
                + xc1.x * xr1.x + xc1.y * xr1.y + xc1.z * xr1.z + xc1.w * xr1.w;

        p += __shfl_xor_sync(0xFFFFFFFFu, p, 4);
        p += __shfl_xor_sync(0xFFFFFFFFu, p, 2);
        p += __shfl_xor_sync(0xFFFFFFFFu, p, 1);

        if (valid) {
            float a = p * w;
            acc0.x = fmaf(a, xc0.x, acc0.x);
            acc0.y = fmaf(a, xc0.y, acc0.y);
            acc0.z = fmaf(a, xc0.z, acc0.z);
            acc0.w = fmaf(a, xc0.w, acc0.w);
            acc1.x = fmaf(a, xc1.x, acc1.x);
            acc1.y = fmaf(a, xc1.y, acc1.y);
            acc1.z = fmaf(a, xc1.z, acc1.z);
            acc1.w = fmaf(a, xc1.w, acc1.w);
        }
    }

    if (any) {
        atomicAdd(&out4[cur_r * 16 + q],     acc0);
        atomicAdd(&out4[cur_r * 16 + 8 + q], acc1);
    }
}

// ---------------------------------------------------------------------------
extern "C" void kernel_launch(void* const* d_in, const int* in_sizes, int n_in,
                              void* d_out, int out_size)
{
    const float4* X4 = (const float4*)d_in[0];
    const float*  W  = (const float*)d_in[1];
    const float*  aw = (const float*)d_in[2];
    const int*   row = (const int*)d_in[3];
    const int*   col = (const int*)d_in[4];

    int n_nodes = in_sizes[0] / D;
    int n_edges = in_sizes[3];

    gemm_zero_kernel<<<(n_nodes + RPB - 1) / RPB, 256>>>(
        X4, W, (float2*)d_out, n_nodes);

    int n_warps  = (n_edges + EPW - 1) / EPW;
    int n_blocks = (n_warps + 7) / 8;
    edge_kernel<<<n_blocks, 256>>>(row, col, aw, (float4*)d_out, n_edges);
}